// round 17
// baseline (speedup 1.0000x reference)
#include <cuda_runtime.h>
#include <cuda_fp16.h>
#include <cstdint>

#define NCHAN 3
#define H 512
#define W 512

// CTA: 64 out rows x 64 out cols, 128 threads = 4 warps.
// warp w: out rows [Yb+16w, +16) as 2 n-groups of 8; all 64 out cols as 4 m-blocks.
// D = A x B per mma: A(16x16) = taps Toeplitz (M = out cols), B(16x8) = data
// (K = input cols, N = out rows).
// Window: input rows Yb-10..Yb+73 (84), cols Xb-16..Xb+79 (96 fp16).
#define WR   84
#define WRB  208                    // 96 fp16 = 192B used; 208 = 13x16B (odd -> conflict-free)
#define OFF_W  0
#define OFF_AF (WR * WRB)           // 17472: tap frags [dy][s][lane] uint4
#define SMEM_TOTAL (OFF_AF + 21 * 3 * 32 * 16)   // + 32256 = 49728 B
#define STG_S 68                    // output staging stride (floats)

typedef uint32_t u32;

__device__ __forceinline__ u32 s2u(const void* p) {
    u32 a;
    asm("{ .reg .u64 t; cvta.to.shared.u64 t, %1; cvt.u32.u64 %0, t; }"
        : "=r"(a) : "l"(p));
    return a;
}
__device__ __forceinline__ void mma_f16(float* d, const u32* a, u32 b0, u32 b1) {
    asm volatile("mma.sync.aligned.m16n8k16.row.col.f32.f16.f16.f32 "
        "{%0,%1,%2,%3}, {%4,%5,%6,%7}, {%8,%9}, {%0,%1,%2,%3};"
        : "+f"(d[0]), "+f"(d[1]), "+f"(d[2]), "+f"(d[3])
        : "r"(a[0]), "r"(a[1]), "r"(a[2]), "r"(a[3]), "r"(b0), "r"(b1));
}
__device__ __forceinline__ void ldmx2(u32& r0, u32& r1, u32 addr) {
    asm volatile("ldmatrix.sync.aligned.m8n8.x2.shared.b16 {%0,%1}, [%2];"
        : "=r"(r0), "=r"(r1) : "r"(addr));
}
__device__ __forceinline__ unsigned short f2h(float v) {
    return __half_as_ushort(__float2half(v));
}
__device__ __forceinline__ u32 tap2(const float* kp, int dy, int dx0) {
    float v0 = (dx0 >= 0 && dx0 <= 20) ? kp[dy * 21 + dx0] : 0.f;
    int dx1 = dx0 + 1;
    float v1 = (dx1 >= 0 && dx1 <= 20) ? kp[dy * 21 + dx1] : 0.f;
    return (u32)f2h(v0) | ((u32)f2h(v1) << 16);
}

__global__ __launch_bounds__(128, 4) void conv_mma(const float* __restrict__ x,
                                                   const float* __restrict__ dk,
                                                   float* __restrict__ dout) {
    extern __shared__ __align__(16) char sm[];
    const u32 smb = s2u(sm);
    const int tid  = threadIdx.x;
    const int w    = tid >> 5;
    const int lane = tid & 31;
    const int img  = blockIdx.z;
    const int Xb   = blockIdx.x * 64;
    const int Yb   = blockIdx.y * 64;

    // ---- A tap frags: A_s[m][kap] = tap[dy][kap - m + 16s - 6] ---------------
    // m16n8k16 row-A frag (verified R16 mapping): g = lane>>2, t = lane&3
    //   a0=(g,2t),(g,2t+1)  a1=(g+8,2t),..  a2=(g,2t+8),..  a3=(g+8,2t+8),..
    const float* kp = dk + (size_t)(img / NCHAN) * 441;
    uint4* Af = reinterpret_cast<uint4*>(sm + OFF_AF);
    for (int e = tid; e < 21 * 3 * 32; e += 128) {
        int dy = e / 96, rem = e % 96;
        int s = rem >> 5, l = rem & 31;
        int g = l >> 2, t2 = (l & 3) * 2;
        int base = 16 * s - 6;
        u32 a0 = tap2(kp, dy, t2 - g + base);
        u32 a1 = tap2(kp, dy, t2 - g - 8 + base);
        u32 a2 = tap2(kp, dy, t2 + 8 - g + base);
        u32 a3 = tap2(kp, dy, t2 - g + base);        // (g+8, 2t+8): dx = t2+8-(g+8)
        Af[e] = make_uint4(a0, a1, a2, a3);
    }

    // ---- window load: fp32 -> fp16, cols Xb-16.. (96), rows Yb-10.. (84) -----
    const float* ximg = x + (size_t)img * H * W;
    for (int i = tid; i < WR * 24; i += 128) {
        int row = i / 24, q = i % 24;
        int gy = Yb - 10 + row, gx = Xb - 16 + 4 * q;
        float4 v = make_float4(0.f, 0.f, 0.f, 0.f);
        if ((unsigned)gy < H) {
            if (gx >= 0 && gx <= W - 4) {
                v = *reinterpret_cast<const float4*>(ximg + (size_t)gy * W + gx);
            } else {
                const float* xr = ximg + (size_t)gy * W;
                if ((unsigned)(gx + 0) < W) v.x = xr[gx + 0];
                if ((unsigned)(gx + 1) < W) v.y = xr[gx + 1];
                if ((unsigned)(gx + 2) < W) v.z = xr[gx + 2];
                if ((unsigned)(gx + 3) < W) v.w = xr[gx + 3];
            }
        }
        uint2 pk = make_uint2((u32)f2h(v.x) | ((u32)f2h(v.y) << 16),
                              (u32)f2h(v.z) | ((u32)f2h(v.w) << 16));
        *reinterpret_cast<uint2*>(sm + OFF_W + (u32)row * WRB + (u32)q * 8) = pk;
    }
    __syncthreads();

    // ---- main loop ------------------------------------------------------------
    float acc[2][4][4];
#pragma unroll
    for (int gg = 0; gg < 2; ++gg)
#pragma unroll
        for (int j = 0; j < 4; ++j)
#pragma unroll
            for (int q = 0; q < 4; ++q) acc[gg][j][q] = 0.f;

    // ldmatrix.x2 per-lane addr: window row = 16w + 8gg + dy + (lane&7),
    // matrix sel (lane>>3)&1 -> +16B; frag f -> +32B.
    const u32 bbase = smb + OFF_W + (u32)(16 * w + (lane & 7)) * WRB
                      + (u32)((lane >> 3) & 1) * 16;

#pragma unroll 1
    for (int dy = 0; dy < 21; ++dy) {
        uint4 A0 = Af[(dy * 3 + 0) * 32 + lane];
        uint4 A1 = Af[(dy * 3 + 1) * 32 + lane];
        uint4 A2 = Af[(dy * 3 + 2) * 32 + lane];
#pragma unroll
        for (int gg = 0; gg < 2; ++gg) {
            const u32 ba = bbase + (u32)(8 * gg + dy) * WRB;
            u32 B0[6], B1[6];
#pragma unroll
            for (int f = 0; f < 6; ++f) ldmx2(B0[f], B1[f], ba + (u32)f * 32);
#pragma unroll
            for (int j = 0; j < 4; ++j) {
                mma_f16(acc[gg][j], &A0.x, B0[j],     B1[j]);
                mma_f16(acc[gg][j], &A1.x, B0[j + 1], B1[j + 1]);
                mma_f16(acc[gg][j], &A2.x, B0[j + 2], B1[j + 2]);
            }
        }
    }

    // ---- epilogue: smem transpose then coalesced STG.128 ----------------------
    // D frag: lane g=lane>>2, t=lane&3: d0=(row 8gg+2t, col 16j+g), d1=(row+1, col),
    //         d2=(row, col+8), d3=(row+1, col+8)   [rows local, cols local]
    __syncthreads();
    float* stg = reinterpret_cast<float*>(sm);
    {
        const int rr = 16 * w + 2 * (lane & 3);
        const int cc = (lane >> 2);
#pragma unroll
        for (int gg = 0; gg < 2; ++gg)
#pragma unroll
            for (int j = 0; j < 4; ++j) {
                int r0 = rr + 8 * gg, c0 = cc + 16 * j;
                stg[(r0)     * STG_S + c0]     = acc[gg][j][0];
                stg[(r0 + 1) * STG_S + c0]     = acc[gg][j][1];
                stg[(r0)     * STG_S + c0 + 8] = acc[gg][j][2];
                stg[(r0 + 1) * STG_S + c0 + 8] = acc[gg][j][3];
            }
    }
    __syncthreads();
    {
        const int rr = tid >> 1;
        const int ch = (tid & 1) * 32;
        float* op = dout + ((size_t)img * H + Yb + rr) * W + Xb + ch;
        const float* sp = stg + rr * STG_S + ch;
#pragma unroll
        for (int i = 0; i < 8; ++i)
            reinterpret_cast<float4*>(op)[i] =
                *reinterpret_cast<const float4*>(sp + 4 * i);
    }
}

extern "C" void kernel_launch(void* const* d_in, const int* in_sizes, int n_in,
                              void* d_out, int out_size) {
    const float* x = (const float*)d_in[0];   // (32,3,512,512) fp32
    const float* k = (const float*)d_in[1];   // (32,1,21,21)  fp32
    float* out = (float*)d_out;

    cudaFuncSetAttribute(conv_mma, cudaFuncAttributeMaxDynamicSharedMemorySize,
                         SMEM_TOTAL);
    dim3 grid(W / 64, H / 64, 96);            // (8, 8, 96)
    conv_mma<<<grid, 128, SMEM_TOTAL>>>(x, k, out);
}